// round 2
// baseline (speedup 1.0000x reference)
#include <cuda_runtime.h>
#include <cstdint>

#define BB 2048
#define SS 2048
#define HH 64
#define MM 32
#define EPSF 1e-6f

// Scratch (device globals; allocation-free per harness rules)
__device__ float g_alpha[MM];
__device__ float g_beta[MM];
__device__ float g_gammap[MM + 1];   // prefix sums of gamma: Gamma_t = sum_{m<min(t,32)} gamma_m
__device__ float g_sig0[BB];
__device__ float g_P[(size_t)BB * SS];

// ---------------------------------------------------------------------------
// Kernel A: compute v_m = fc_w * A^m (row-vector), alpha/beta/gamma, Gamma prefix
// ---------------------------------------------------------------------------
__global__ void setup_kernel(const float* __restrict__ Wih_w,
                             const float* __restrict__ Wih_b,
                             const float* __restrict__ Whh_w,
                             const float* __restrict__ Whh_b,
                             const float* __restrict__ fc_w) {
    __shared__ float v[HH];
    __shared__ float Wsh[HH * HH];
    __shared__ float r3[2][3];
    const int tid = threadIdx.x;           // 64 threads
    const int lane = tid & 31;
    const int warp = tid >> 5;

    for (int i = tid; i < HH * HH; i += 64) Wsh[i] = Whh_w[i];
    const float w1 = Wih_w[tid * 2 + 0];
    const float w2 = Wih_w[tid * 2 + 1];
    const float bt = Wih_b[tid] + Whh_b[tid];
    v[tid] = fc_w[tid];
    __syncthreads();

    for (int m = 0; m < MM; m++) {
        const float vk = v[tid];
        float pa = vk * w2, pb = vk * w1, pg = vk * bt;
        #pragma unroll
        for (int o = 16; o > 0; o >>= 1) {
            pa += __shfl_xor_sync(0xFFFFFFFFu, pa, o);
            pb += __shfl_xor_sync(0xFFFFFFFFu, pb, o);
            pg += __shfl_xor_sync(0xFFFFFFFFu, pg, o);
        }
        if (lane == 0) { r3[warp][0] = pa; r3[warp][1] = pb; r3[warp][2] = pg; }
        __syncthreads();
        if (tid == 0) {
            g_alpha[m]      = r3[0][0] + r3[1][0];
            g_beta[m]       = r3[0][1] + r3[1][1];
            g_gammap[m + 1] = r3[0][2] + r3[1][2];   // raw gamma_m; prefix below
        }
        // v_{m+1}[k] = sum_j v_m[j] * W[j,k]
        float acc = 0.f;
        #pragma unroll
        for (int j = 0; j < HH; j++) acc = fmaf(v[j], Wsh[j * HH + tid], acc);
        __syncthreads();
        v[tid] = acc;
        __syncthreads();
    }
    if (tid == 0) {
        g_gammap[0] = 0.f;
        float run = 0.f;
        for (int m = 0; m < MM; m++) { run += g_gammap[m + 1]; g_gammap[m + 1] = run; }
    }
}

// ---------------------------------------------------------------------------
// Kernel B: per-batch variance (ddof=1) + precompute
//   P[b,t] = fc_b + Gamma_min(t,32) + sum_{m=0}^{min(t-1,31)} beta_m * res[b,t-1-m]^2
// ---------------------------------------------------------------------------
__global__ __launch_bounds__(256) void prep_kernel(const float* __restrict__ residuals,
                                                   const float* __restrict__ fc_b) {
    __shared__ float sh[SS];
    __shared__ float beta_s[MM];
    __shared__ float gp_s[MM + 1];
    __shared__ float rs[8], rq[8];
    const int b = blockIdx.x;
    const int tid = threadIdx.x;
    const float* __restrict__ row = residuals + (size_t)b * SS;

    float sum = 0.f, sq = 0.f;
    for (int i = tid; i < SS; i += 256) {
        float x = row[i];
        sh[i] = x;
        sum += x;
        sq = fmaf(x, x, sq);
    }
    if (tid < MM)     beta_s[tid] = g_beta[tid];
    if (tid < MM + 1) gp_s[tid]   = g_gammap[tid];

    #pragma unroll
    for (int o = 16; o > 0; o >>= 1) {
        sum += __shfl_xor_sync(0xFFFFFFFFu, sum, o);
        sq  += __shfl_xor_sync(0xFFFFFFFFu, sq,  o);
    }
    const int w = tid >> 5;
    if ((tid & 31) == 0) { rs[w] = sum; rq[w] = sq; }
    __syncthreads();   // sh + rs/rq + beta_s visible

    if (tid == 0) {
        float ts = 0.f, tq = 0.f;
        #pragma unroll
        for (int i = 0; i < 8; i++) { ts += rs[i]; tq += rq[i]; }
        g_sig0[b] = (tq - ts * ts / (float)SS) / (float)(SS - 1);
    }
    // square in place (each thread owns the elements it loaded)
    for (int i = tid; i < SS; i += 256) { float x = sh[i]; sh[i] = x * x; }
    __syncthreads();

    const float fcb = fc_b[0];
    for (int t = tid; t < SS; t += 256) {
        float acc = fcb + gp_s[t < MM ? t : MM];
        if (t >= MM + 1) {
            #pragma unroll
            for (int m = 0; m < MM; m++)
                acc = fmaf(beta_s[m], sh[t - 1 - m], acc);
        } else {
            #pragma unroll
            for (int m = 0; m < MM; m++) {
                int idx = t - 1 - m;
                if (idx >= 0) acc = fmaf(beta_s[m], sh[idx], acc);
            }
        }
        g_P[(size_t)b * SS + t] = acc;
    }
}

// ---------------------------------------------------------------------------
// Kernel C: serial recurrence. lane = batch. 32-step unrolled register ring.
//   sigma_t = softplus( P[b,t] + sum_{m=0}^{31} alpha_m * sigma_{t-1-m} ) + EPS
// ---------------------------------------------------------------------------
__global__ __launch_bounds__(32) void rec_kernel(float* __restrict__ out) {
    const int lane = threadIdx.x;
    const int b = blockIdx.x * 32 + lane;

    float a[MM];
    #pragma unroll
    for (int m = 0; m < MM; m++) a[m] = g_alpha[m];

    float s[MM];
    #pragma unroll
    for (int m = 0; m < MM; m++) s[m] = 0.f;
    const float sig0 = g_sig0[b];
    s[0] = sig0;

    const float4* __restrict__ Pv = (const float4*)(g_P + (size_t)b * SS);
    float4* __restrict__ Ov = (float4*)(out + (size_t)b * SS);
    float4 p4 = Pv[0];
    float4 ov;

    for (int base = 0; base < SS; base += 32) {
        #pragma unroll
        for (int j = 0; j < 32; j++) {
            if ((j & 3) == 0) p4 = Pv[(base + j) >> 2];
            float px;
            if      ((j & 3) == 0) px = p4.x;
            else if ((j & 3) == 1) px = p4.y;
            else if ((j & 3) == 2) px = p4.z;
            else                   px = p4.w;

            // partial sum over m=1..31 (depends only on sigma_{<= t-2}: overlaps
            // previous step's softplus); alpha_0 * sigma_{t-1} applied last.
            float accs[4] = {px, 0.f, 0.f, 0.f};
            #pragma unroll
            for (int m = 1; m < MM; m++)
                accs[m & 3] = fmaf(a[m], s[(j - 1 - m) & 31], accs[m & 3]);
            float part = (accs[0] + accs[1]) + (accs[2] + accs[3]);
            float x = fmaf(a[0], s[(j - 1) & 31], part);

            // softplus(x) = max(x,0) + log1p(exp(-|x|))
            float sp = fmaxf(x, 0.f) + __logf(1.f + __expf(-fabsf(x)));
            float sig = sp + EPSF;
            if (base + j == 0) sig = sig0;   // t=0 output is the variance
            s[j & 31] = sig;

            if      ((j & 3) == 0) ov.x = sig;
            else if ((j & 3) == 1) ov.y = sig;
            else if ((j & 3) == 2) ov.z = sig;
            else                   ov.w = sig;
            if ((j & 3) == 3) Ov[(base + j) >> 2] = ov;
        }
    }
}

// ---------------------------------------------------------------------------
extern "C" void kernel_launch(void* const* d_in, const int* in_sizes, int n_in,
                              void* d_out, int out_size) {
    const float* residuals = (const float*)d_in[0];  // (B,S)
    const float* W_ih_w    = (const float*)d_in[1];  // (H,2)
    const float* W_ih_b    = (const float*)d_in[2];  // (H,)
    const float* W_hh_w    = (const float*)d_in[3];  // (H,H)
    const float* W_hh_b    = (const float*)d_in[4];  // (H,)
    const float* fc_w      = (const float*)d_in[5];  // (1,H)
    const float* fc_b      = (const float*)d_in[6];  // (1,)
    float* out = (float*)d_out;                      // (B,S)

    setup_kernel<<<1, 64>>>(W_ih_w, W_ih_b, W_hh_w, W_hh_b, fc_w);
    prep_kernel<<<BB, 256>>>(residuals, fc_b);
    rec_kernel<<<BB / 32, 32>>>(out);
}

// round 3
// speedup vs baseline: 1.0249x; 1.0249x over previous
#include <cuda_runtime.h>
#include <cstdint>

#define BB 2048
#define SS 2048
#define HH 64
#define MM 32          // taps kept in setup/prep (beta/gamma)
#define MR 24          // taps in the serial alpha recurrence
#define EPSF 1e-6f
#define L2E 1.4426950408889634f
#define LN2 0.6931471805599453f

// Scratch (device globals; allocation-free per harness rules)
// NOTE: alpha/beta/gammap and P are pre-scaled by log2(e) so the recurrence
// works directly in the log2 domain (saves one on-chain FMUL per step).
__device__ float g_alpha[MM];
__device__ float g_beta[MM];
__device__ float g_gammap[MM + 1];
__device__ float g_sig0[BB];
__device__ float g_P[(size_t)BB * SS + 4];   // +4 pad: rec prefetches one float4 past the end

__device__ __forceinline__ float ex2f(float x) { float y; asm("ex2.approx.f32 %0, %1;" : "=f"(y) : "f"(x)); return y; }
__device__ __forceinline__ float lg2f(float x) { float y; asm("lg2.approx.f32 %0, %1;" : "=f"(y) : "f"(x)); return y; }

// ---------------------------------------------------------------------------
// Kernel A: v_m = fc_w * A^m; alpha_m = v_m.w2, beta_m = v_m.w1, gamma_m = v_m.b
// 256 threads: matvec split 4-way per column; reductions deferred to the end.
// ---------------------------------------------------------------------------
__global__ __launch_bounds__(256) void setup_kernel(const float* __restrict__ Wih_w,
                                                    const float* __restrict__ Wih_b,
                                                    const float* __restrict__ Whh_w,
                                                    const float* __restrict__ Whh_b,
                                                    const float* __restrict__ fc_w) {
    __shared__ float Wsh[HH * HH];
    __shared__ float vs[MM][HH];        // v_m for m = 0..31
    __shared__ float pacc[4][HH];
    __shared__ float w1s[HH], w2s[HH], bts[HH];
    __shared__ float sg[MM];
    const int tid = threadIdx.x;
    const int col = tid & 63, part = tid >> 6;

    for (int i = tid; i < HH * HH; i += 256) Wsh[i] = Whh_w[i];
    if (tid < HH) {
        w1s[tid] = Wih_w[tid * 2 + 0];
        w2s[tid] = Wih_w[tid * 2 + 1];
        bts[tid] = Wih_b[tid] + Whh_b[tid];
        vs[0][tid] = fc_w[tid];
    }
    __syncthreads();

    // v_{m+1}[col] = sum_j v_m[j] * W[j][col], split over 4 partials
    for (int m = 0; m < MM - 1; m++) {
        float a0 = 0.f, a1 = 0.f, a2 = 0.f, a3 = 0.f;
        const int jb = part * 16;
        #pragma unroll
        for (int jj = 0; jj < 16; jj += 4) {
            a0 = fmaf(vs[m][jb + jj + 0], Wsh[(jb + jj + 0) * HH + col], a0);
            a1 = fmaf(vs[m][jb + jj + 1], Wsh[(jb + jj + 1) * HH + col], a1);
            a2 = fmaf(vs[m][jb + jj + 2], Wsh[(jb + jj + 2) * HH + col], a2);
            a3 = fmaf(vs[m][jb + jj + 3], Wsh[(jb + jj + 3) * HH + col], a3);
        }
        pacc[part][col] = (a0 + a1) + (a2 + a3);
        __syncthreads();
        if (part == 0)
            vs[m + 1][col] = (pacc[0][col] + pacc[1][col]) + (pacc[2][col] + pacc[3][col]);
        __syncthreads();
    }

    // Reductions: warp w handles m = r*8 + w, lane sums 2 elements each.
    const int wrp = tid >> 5, ln = tid & 31;
    for (int r = 0; r < 4; r++) {
        const int m = r * 8 + wrp;
        const float v0 = vs[m][ln], v1 = vs[m][ln + 32];
        float pa = fmaf(v1, w2s[ln + 32], v0 * w2s[ln]);
        float pb = fmaf(v1, w1s[ln + 32], v0 * w1s[ln]);
        float pg = fmaf(v1, bts[ln + 32], v0 * bts[ln]);
        #pragma unroll
        for (int o = 16; o > 0; o >>= 1) {
            pa += __shfl_xor_sync(0xFFFFFFFFu, pa, o);
            pb += __shfl_xor_sync(0xFFFFFFFFu, pb, o);
            pg += __shfl_xor_sync(0xFFFFFFFFu, pg, o);
        }
        if (ln == 0) { g_alpha[m] = pa * L2E; g_beta[m] = pb * L2E; sg[m] = pg * L2E; }
    }
    __syncthreads();
    if (tid == 0) {
        g_gammap[0] = 0.f;
        float run = 0.f;
        #pragma unroll
        for (int m = 0; m < MM; m++) { run += sg[m]; g_gammap[m + 1] = run; }
    }
}

// ---------------------------------------------------------------------------
// Kernel B: per-batch variance (ddof=1) + precompute (log2-scaled)
//   P[b,t] = L2E*fc_b + Gammap[min(t,32)] + sum_m beta'_m * res[b,t-1-m]^2
// ---------------------------------------------------------------------------
__global__ __launch_bounds__(256) void prep_kernel(const float* __restrict__ residuals,
                                                   const float* __restrict__ fc_b) {
    __shared__ float sh[SS];            // squared residuals
    __shared__ float beta_s[MM];
    __shared__ float gp_s[MM + 1];
    __shared__ float rs[8], rq[8];
    const int b = blockIdx.x;
    const int tid = threadIdx.x;
    const float4* __restrict__ row4 = (const float4*)(residuals + (size_t)b * SS);
    float4* __restrict__ sh4 = (float4*)sh;

    float sum = 0.f, sq = 0.f;
    for (int i = tid; i < SS / 4; i += 256) {
        float4 x = row4[i];
        sum += (x.x + x.y) + (x.z + x.w);
        float s0 = x.x * x.x, s1 = x.y * x.y, s2 = x.z * x.z, s3 = x.w * x.w;
        sq += (s0 + s1) + (s2 + s3);
        sh4[i] = make_float4(s0, s1, s2, s3);
    }
    if (tid < MM)     beta_s[tid] = g_beta[tid];
    if (tid < MM + 1) gp_s[tid]   = g_gammap[tid];

    #pragma unroll
    for (int o = 16; o > 0; o >>= 1) {
        sum += __shfl_xor_sync(0xFFFFFFFFu, sum, o);
        sq  += __shfl_xor_sync(0xFFFFFFFFu, sq,  o);
    }
    const int w = tid >> 5;
    if ((tid & 31) == 0) { rs[w] = sum; rq[w] = sq; }
    __syncthreads();

    if (tid == 0) {
        float ts = 0.f, tq = 0.f;
        #pragma unroll
        for (int i = 0; i < 8; i++) { ts += rs[i]; tq += rq[i]; }
        g_sig0[b] = (tq - ts * ts / (float)SS) / (float)(SS - 1);
    }

    const float fcb = fc_b[0] * L2E;
    float* __restrict__ Prow = g_P + (size_t)b * SS;
    for (int t = tid; t < SS; t += 256) {
        float acc = fcb + gp_s[t < MM ? t : MM];
        if (t >= MM + 1) {
            #pragma unroll
            for (int m = 0; m < MM; m++)
                acc = fmaf(beta_s[m], sh[t - 1 - m], acc);
        } else {
            #pragma unroll
            for (int m = 0; m < MM; m++) {
                int idx = t - 1 - m;
                if (idx >= 0) acc = fmaf(beta_s[m], sh[idx], acc);
            }
        }
        Prow[t] = acc;
    }
}

// ---------------------------------------------------------------------------
// Kernel C: serial recurrence, lane = batch. Log2-domain softplus, EPS folded
// off-chain, one-group-ahead P prefetch. Chain/step ~ 44 cyc.
// ---------------------------------------------------------------------------
template <bool FIRST>
__device__ __forceinline__ void rec_block(int base, float (&s)[32], float& sp,
                                          float4& p4, const float4* __restrict__ Pv,
                                          float4* __restrict__ Ov,
                                          const float (&a)[MR], float a0eps, float sig0) {
    float4 cur, ov;
    #pragma unroll
    for (int j = 0; j < 32; j++) {
        if ((j & 3) == 0) { cur = p4; p4 = Pv[((base + j) >> 2) + 1]; }
        float px;
        if      ((j & 3) == 0) px = cur.x;
        else if ((j & 3) == 1) px = cur.y;
        else if ((j & 3) == 2) px = cur.z;
        else                   px = cur.w;

        // off-chain partial: taps m = 1..MR-1 (oldest deps, 4 accumulators)
        float accs[4] = {px + a0eps, 0.f, 0.f, 0.f};
        #pragma unroll
        for (int m = 1; m < MR; m++)
            accs[m & 3] = fmaf(a[m], s[(j - 1 - m) & 31], accs[m & 3]);
        float part = (accs[0] + accs[1]) + (accs[2] + accs[3]);

        // chain: x2 = L2E * x
        float x2 = fmaf(a[0], sp, part);
        float e  = ex2f(-fabsf(x2));
        float lg = lg2f(1.f + e);
        float mx = fmaxf(x2, 0.f) * LN2;
        sp = fmaf(lg, LN2, mx);            // softplus(x), EPS excluded
        float sig = sp + EPSF;
        if (FIRST && (j == 0)) { sig = sig0; sp = sig0 - EPSF; }
        s[j & 31] = sig;

        if      ((j & 3) == 0) ov.x = sig;
        else if ((j & 3) == 1) ov.y = sig;
        else if ((j & 3) == 2) ov.z = sig;
        else                   ov.w = sig;
        if ((j & 3) == 3) Ov[(base + j) >> 2] = ov;
    }
}

__global__ __launch_bounds__(32) void rec_kernel(float* __restrict__ out) {
    const int lane = threadIdx.x;
    const int b = blockIdx.x * 32 + lane;

    float a[MR];
    #pragma unroll
    for (int m = 0; m < MR; m++) a[m] = g_alpha[m];
    const float a0eps = a[0] * EPSF;

    float s[32];
    #pragma unroll
    for (int m = 0; m < 32; m++) s[m] = 0.f;
    const float sig0 = g_sig0[b];
    s[0] = sig0;
    float sp = sig0 - EPSF;

    const float4* __restrict__ Pv = (const float4*)(g_P + (size_t)b * SS);
    float4* __restrict__ Ov = (float4*)(out + (size_t)b * SS);
    float4 p4 = Pv[0];

    rec_block<true>(0, s, sp, p4, Pv, Ov, a, a0eps, sig0);
    for (int base = 32; base < SS; base += 32)
        rec_block<false>(base, s, sp, p4, Pv, Ov, a, a0eps, sig0);
}

// ---------------------------------------------------------------------------
extern "C" void kernel_launch(void* const* d_in, const int* in_sizes, int n_in,
                              void* d_out, int out_size) {
    const float* residuals = (const float*)d_in[0];  // (B,S)
    const float* W_ih_w    = (const float*)d_in[1];  // (H,2)
    const float* W_ih_b    = (const float*)d_in[2];  // (H,)
    const float* W_hh_w    = (const float*)d_in[3];  // (H,H)
    const float* W_hh_b    = (const float*)d_in[4];  // (H,)
    const float* fc_w      = (const float*)d_in[5];  // (1,H)
    const float* fc_b      = (const float*)d_in[6];  // (1,)
    float* out = (float*)d_out;                      // (B,S)

    setup_kernel<<<1, 256>>>(W_ih_w, W_ih_b, W_hh_w, W_hh_b, fc_w);
    prep_kernel<<<BB, 256>>>(residuals, fc_b);
    rec_kernel<<<BB / 32, 32>>>(out);
}

// round 6
// speedup vs baseline: 1.1446x; 1.1168x over previous
#include <cuda_runtime.h>
#include <cstdint>

#define BB 2048
#define SS 2048
#define HH 64
#define MM 24          // taps in setup/prep (beta/gamma)
#define MR 20          // taps in the serial alpha recurrence
#define EPSF 1e-6f
#define L2E 1.4426950408889634f
#define LN2 0.6931471805599453f

// Scratch (device globals; allocation-free per harness rules)
// alpha/beta/gammap and P are pre-scaled by log2(e): recurrence in log2 domain.
__device__ float g_alpha[MM];
__device__ float g_beta[MM];
__device__ float g_gammap[MM + 1];
__device__ float g_sig0[BB];
__device__ float g_P[(size_t)BB * SS + 4];   // +4 pad for one-ahead prefetch

__device__ __forceinline__ float ex2f(float x) { float y; asm("ex2.approx.f32 %0, %1;" : "=f"(y) : "f"(x)); return y; }
__device__ __forceinline__ float lg2f(float x) { float y; asm("lg2.approx.f32 %0, %1;" : "=f"(y) : "f"(x)); return y; }

// ---------------------------------------------------------------------------
// Kernel A: v_m = fc_w * A^m; alpha_m = v_m.w2, beta_m = v_m.w1, gamma_m = v_m.b
// ---------------------------------------------------------------------------
__global__ __launch_bounds__(256) void setup_kernel(const float* __restrict__ Wih_w,
                                                    const float* __restrict__ Wih_b,
                                                    const float* __restrict__ Whh_w,
                                                    const float* __restrict__ Whh_b,
                                                    const float* __restrict__ fc_w) {
    __shared__ float Wsh[HH * HH];
    __shared__ float vs[MM][HH];
    __shared__ float pacc[4][HH];
    __shared__ float w1s[HH], w2s[HH], bts[HH];
    __shared__ float sg[MM];
    const int tid = threadIdx.x;
    const int col = tid & 63, part = tid >> 6;

    for (int i = tid; i < HH * HH; i += 256) Wsh[i] = Whh_w[i];
    if (tid < HH) {
        w1s[tid] = Wih_w[tid * 2 + 0];
        w2s[tid] = Wih_w[tid * 2 + 1];
        bts[tid] = Wih_b[tid] + Whh_b[tid];
        vs[0][tid] = fc_w[tid];
    }
    __syncthreads();

    for (int m = 0; m < MM - 1; m++) {
        float a0 = 0.f, a1 = 0.f, a2 = 0.f, a3 = 0.f;
        const int jb = part * 16;
        #pragma unroll
        for (int jj = 0; jj < 16; jj += 4) {
            a0 = fmaf(vs[m][jb + jj + 0], Wsh[(jb + jj + 0) * HH + col], a0);
            a1 = fmaf(vs[m][jb + jj + 1], Wsh[(jb + jj + 1) * HH + col], a1);
            a2 = fmaf(vs[m][jb + jj + 2], Wsh[(jb + jj + 2) * HH + col], a2);
            a3 = fmaf(vs[m][jb + jj + 3], Wsh[(jb + jj + 3) * HH + col], a3);
        }
        pacc[part][col] = (a0 + a1) + (a2 + a3);
        __syncthreads();
        if (part == 0)
            vs[m + 1][col] = (pacc[0][col] + pacc[1][col]) + (pacc[2][col] + pacc[3][col]);
        __syncthreads();
    }

    // Reductions: warp w handles m = r*8 + w.
    const int wrp = tid >> 5, ln = tid & 31;
    for (int r = 0; r < MM / 8; r++) {
        const int m = r * 8 + wrp;
        const float v0 = vs[m][ln], v1 = vs[m][ln + 32];
        float pa = fmaf(v1, w2s[ln + 32], v0 * w2s[ln]);
        float pb = fmaf(v1, w1s[ln + 32], v0 * w1s[ln]);
        float pg = fmaf(v1, bts[ln + 32], v0 * bts[ln]);
        #pragma unroll
        for (int o = 16; o > 0; o >>= 1) {
            pa += __shfl_xor_sync(0xFFFFFFFFu, pa, o);
            pb += __shfl_xor_sync(0xFFFFFFFFu, pb, o);
            pg += __shfl_xor_sync(0xFFFFFFFFu, pg, o);
        }
        if (ln == 0) { g_alpha[m] = pa * L2E; g_beta[m] = pb * L2E; sg[m] = pg * L2E; }
    }
    __syncthreads();
    if (tid == 0) {
        g_gammap[0] = 0.f;
        float run = 0.f;
        #pragma unroll
        for (int m = 0; m < MM; m++) { run += sg[m]; g_gammap[m + 1] = run; }
    }
}

// ---------------------------------------------------------------------------
// Kernel B: variance (ddof=1) + P precompute, register-blocked convolution.
// ---------------------------------------------------------------------------
__global__ __launch_bounds__(256) void prep_kernel(const float* __restrict__ residuals,
                                                   const float* __restrict__ fc_b) {
    __shared__ float sh[SS];            // squared residuals
    __shared__ float beta_s[MM];
    __shared__ float gp_s[MM + 1];
    __shared__ float rs[8], rq[8];
    const int b = blockIdx.x;
    const int tid = threadIdx.x;
    const float4* __restrict__ row4 = (const float4*)(residuals + (size_t)b * SS);
    float4* __restrict__ sh4 = (float4*)sh;

    float sum = 0.f, sq = 0.f;
    for (int i = tid; i < SS / 4; i += 256) {
        float4 x = row4[i];
        sum += (x.x + x.y) + (x.z + x.w);
        float s0 = x.x * x.x, s1 = x.y * x.y, s2 = x.z * x.z, s3 = x.w * x.w;
        sq += (s0 + s1) + (s2 + s3);
        sh4[i] = make_float4(s0, s1, s2, s3);
    }
    if (tid < MM)     beta_s[tid] = g_beta[tid];
    if (tid < MM + 1) gp_s[tid]   = g_gammap[tid];

    #pragma unroll
    for (int o = 16; o > 0; o >>= 1) {
        sum += __shfl_xor_sync(0xFFFFFFFFu, sum, o);
        sq  += __shfl_xor_sync(0xFFFFFFFFu, sq,  o);
    }
    const int w = tid >> 5;
    if ((tid & 31) == 0) { rs[w] = sum; rq[w] = sq; }
    __syncthreads();

    if (tid == 0) {
        float ts = 0.f, tq = 0.f;
        #pragma unroll
        for (int i = 0; i < 8; i++) { ts += rs[i]; tq += rq[i]; }
        g_sig0[b] = (tq - ts * ts / (float)SS) / (float)(SS - 1);
    }

    // Register-blocked convolution: thread handles t in [tid*8, tid*8+8).
    const float fcb = fc_b[0] * L2E;
    float* __restrict__ Prow = g_P + (size_t)b * SS;
    const int t0 = tid * 8;

    float wv[32];
    #pragma unroll
    for (int k = 0; k < 32; k++) {
        int idx = t0 - MM + k;
        wv[k] = (idx >= 0) ? sh[idx] : 0.f;
    }
    float o8[8];
    #pragma unroll
    for (int jj = 0; jj < 8; jj++) {
        int t = t0 + jj;
        float acc = fcb + gp_s[t < MM ? t : MM];
        #pragma unroll
        for (int m = 0; m < MM; m++)
            acc = fmaf(beta_s[m], wv[jj + (MM - 1) - m], acc);
        o8[jj] = acc;
    }
    float4* __restrict__ Pv = (float4*)(Prow + t0);
    Pv[0] = make_float4(o8[0], o8[1], o8[2], o8[3]);
    Pv[1] = make_float4(o8[4], o8[5], o8[6], o8[7]);
}

// ---------------------------------------------------------------------------
// Kernel C: serial recurrence, 2 lanes per batch (A = lane<16, B = lane>=16).
// Both lanes run the chain redundantly (warp stays converged); far taps
// (m=4..19) are computed 2+ steps ahead: on even j, A builds the partial for
// step j+4, B for j+5, over the same ring window; one shfl_xor(16) per 2 steps.
// Near taps m=1..3 (even t) / 1..4 (odd t) are per-step. Chain: ex2->add->lg2->fma.
// ---------------------------------------------------------------------------
template <bool FIRST>
__device__ __forceinline__ void rec_block(
    float (&s)[32], float (&pend)[8], float& lgc, float& mxc,
    float4& p4, const float4* __restrict__ Pv, float4* __restrict__ Ov, int base,
    const float (&c)[16], float a0r, float a1, float a2, float a3, float a4v,
    float a0eps, float sig0, bool laneA) {
    float4 cur, ov;
    #pragma unroll
    for (int j = 0; j < 32; j++) {
        if ((j & 3) == 0) { cur = p4; p4 = Pv[((base + j) >> 2) + 1]; }
        float px;
        if      ((j & 3) == 0) px = cur.x;
        else if ((j & 3) == 1) px = cur.y;
        else if ((j & 3) == 2) px = cur.z;
        else                   px = cur.w;

        // off-chain accumulator: P + eps-fold + far partial + near taps
        float acc = px + a0eps + pend[j & 7];
        acc = fmaf(a1, s[(j + 30) & 31], acc);     // sigma_{t-2}
        acc = fmaf(a2, s[(j + 29) & 31], acc);     // sigma_{t-3}
        acc = fmaf(a3, s[(j + 28) & 31], acc);     // sigma_{t-4}
        if (j & 1) acc = fmaf(a4v, s[(j + 27) & 31], acc);  // odd t: m=4 near

        // chain (40 cyc): carried (mxc,lgc) encode sigma_{t-1}
        float acc2 = fmaf(a0r, mxc, acc);
        float x2   = fmaf(a0r, lgc, acc2);
        float e  = ex2f(-fabsf(x2));
        float mx = fmaxf(x2, 0.f);
        float lg = lg2f(1.f + e);
        float sig = fmaf(LN2, lg, fmaf(LN2, mx, EPSF));
        if (FIRST && j == 0) { sig = sig0; mx = L2E * (sig0 - EPSF); lg = 0.f; }
        mxc = mx; lgc = lg;
        s[j & 31] = sig;

        // far production every other step
        if ((j & 1) == 0) {
            float f0 = 0.f, f1 = 0.f, f2 = 0.f, f3 = 0.f;
            #pragma unroll
            for (int i = 0; i < 16; i++) {
                float sv = s[(j + 31 - i) & 31];   // sigma_{t-1-i}
                if      ((i & 3) == 0) f0 = fmaf(c[i], sv, f0);
                else if ((i & 3) == 1) f1 = fmaf(c[i], sv, f1);
                else if ((i & 3) == 2) f2 = fmaf(c[i], sv, f2);
                else                   f3 = fmaf(c[i], sv, f3);
            }
            float fs = (f0 + f1) + (f2 + f3);
            float other = __shfl_xor_sync(0xFFFFFFFFu, fs, 16);
            // A's sum targets j+4, B's targets j+5
            pend[(j + 4) & 7] = laneA ? fs : other;
            pend[(j + 5) & 7] = laneA ? other : fs;
        }

        if      ((j & 3) == 0) ov.x = sig;
        else if ((j & 3) == 1) ov.y = sig;
        else if ((j & 3) == 2) ov.z = sig;
        else                   ov.w = sig;
        if (((j & 3) == 3) && laneA) Ov[(base + j) >> 2] = ov;
    }
}

__global__ __launch_bounds__(32) void rec_kernel(float* __restrict__ out) {
    const int lane = threadIdx.x;
    const bool laneA = lane < 16;
    const int b = blockIdx.x * 16 + (lane & 15);

    // far coefficients: A: alpha[4+i]; B: alpha[5+i] (zero-padded past MR)
    float c[16];
    #pragma unroll
    for (int i = 0; i < 16; i++) {
        int m = (laneA ? 4 : 5) + i;
        c[i] = (m < MR) ? g_alpha[m] : 0.f;
    }
    const float a0r   = g_alpha[0] * LN2;   // = raw alpha_0
    const float a1    = g_alpha[1];
    const float a2    = g_alpha[2];
    const float a3    = g_alpha[3];
    const float a4v   = g_alpha[4];
    const float a0eps = g_alpha[0] * EPSF;

    float s[32];
    #pragma unroll
    for (int i = 0; i < 32; i++) s[i] = 0.f;
    float pend[8];
    #pragma unroll
    for (int i = 0; i < 8; i++) pend[i] = 0.f;

    const float sig0 = g_sig0[b];
    float lgc = 0.f, mxc = 0.f;   // sigma_{-1} = 0 (step 0 overridden anyway)

    const float4* __restrict__ Pv = (const float4*)(g_P + (size_t)b * SS);
    float4* __restrict__ Ov = (float4*)(out + (size_t)b * SS);
    float4 p4 = Pv[0];

    rec_block<true>(s, pend, lgc, mxc, p4, Pv, Ov, 0, c, a0r, a1, a2, a3, a4v, a0eps, sig0, laneA);
    for (int base = 32; base < SS; base += 32)
        rec_block<false>(s, pend, lgc, mxc, p4, Pv, Ov, base, c, a0r, a1, a2, a3, a4v, a0eps, sig0, laneA);
}

// ---------------------------------------------------------------------------
extern "C" void kernel_launch(void* const* d_in, const int* in_sizes, int n_in,
                              void* d_out, int out_size) {
    const float* residuals = (const float*)d_in[0];  // (B,S)
    const float* W_ih_w    = (const float*)d_in[1];  // (H,2)
    const float* W_ih_b    = (const float*)d_in[2];  // (H,)
    const float* W_hh_w    = (const float*)d_in[3];  // (H,H)
    const float* W_hh_b    = (const float*)d_in[4];  // (H,)
    const float* fc_w      = (const float*)d_in[5];  // (1,H)
    const float* fc_b      = (const float*)d_in[6];  // (1,)
    float* out = (float*)d_out;                      // (B,S)

    setup_kernel<<<1, 256>>>(W_ih_w, W_ih_b, W_hh_w, W_hh_b, fc_w);
    prep_kernel<<<BB, 256>>>(residuals, fc_b);
    rec_kernel<<<BB / 16, 32>>>(out);
}

// round 8
// speedup vs baseline: 1.1577x; 1.0114x over previous
#include <cuda_runtime.h>
#include <cstdint>

#define BB 2048
#define SS 2048
#define HH 64
#define MM 16          // taps in setup/prep (beta/gamma)
#define MR 12          // taps in the serial alpha recurrence
#define EPSF 1e-6f
#define L2E 1.4426950408889634f
#define LN2 0.6931471805599453f

// Scratch (device globals; allocation-free per harness rules)
// alpha/beta/gammap and P are pre-scaled by log2(e): recurrence in log2 domain.
__device__ float g_alpha[MM];     // L2E * alpha_raw
__device__ float g_beta[MM];      // L2E * beta_raw
__device__ float g_gammap[MM + 1];
__device__ float g_epsfold;       // EPSF * sum_{m<MR} g_alpha[m]
__device__ float g_sig0[BB];
__device__ float g_P[(size_t)BB * SS + 4];   // +4 pad for one-ahead prefetch

__device__ __forceinline__ float ex2f(float x) { float y; asm("ex2.approx.f32 %0, %1;" : "=f"(y) : "f"(x)); return y; }
__device__ __forceinline__ float lg2f(float x) { float y; asm("lg2.approx.f32 %0, %1;" : "=f"(y) : "f"(x)); return y; }

// ---------------------------------------------------------------------------
// Kernel A: v_m = fc_w * A^m; alpha_m = v_m.w2, beta_m = v_m.w1, gamma_m = v_m.b
// ---------------------------------------------------------------------------
__global__ __launch_bounds__(256) void setup_kernel(const float* __restrict__ Wih_w,
                                                    const float* __restrict__ Wih_b,
                                                    const float* __restrict__ Whh_w,
                                                    const float* __restrict__ Whh_b,
                                                    const float* __restrict__ fc_w) {
    __shared__ float Wsh[HH * HH];
    __shared__ float vs[MM][HH];
    __shared__ float pacc[4][HH];
    __shared__ float w1s[HH], w2s[HH], bts[HH];
    __shared__ float sg[MM], sa[MM];
    const int tid = threadIdx.x;
    const int col = tid & 63, part = tid >> 6;

    for (int i = tid; i < HH * HH; i += 256) Wsh[i] = Whh_w[i];
    if (tid < HH) {
        w1s[tid] = Wih_w[tid * 2 + 0];
        w2s[tid] = Wih_w[tid * 2 + 1];
        bts[tid] = Wih_b[tid] + Whh_b[tid];
        vs[0][tid] = fc_w[tid];
    }
    __syncthreads();

    for (int m = 0; m < MM - 1; m++) {
        float a0 = 0.f, a1 = 0.f, a2 = 0.f, a3 = 0.f;
        const int jb = part * 16;
        #pragma unroll
        for (int jj = 0; jj < 16; jj += 4) {
            a0 = fmaf(vs[m][jb + jj + 0], Wsh[(jb + jj + 0) * HH + col], a0);
            a1 = fmaf(vs[m][jb + jj + 1], Wsh[(jb + jj + 1) * HH + col], a1);
            a2 = fmaf(vs[m][jb + jj + 2], Wsh[(jb + jj + 2) * HH + col], a2);
            a3 = fmaf(vs[m][jb + jj + 3], Wsh[(jb + jj + 3) * HH + col], a3);
        }
        pacc[part][col] = (a0 + a1) + (a2 + a3);
        __syncthreads();
        if (part == 0)
            vs[m + 1][col] = (pacc[0][col] + pacc[1][col]) + (pacc[2][col] + pacc[3][col]);
        __syncthreads();
    }

    // Reductions: warp w handles m = r*8 + w.
    const int wrp = tid >> 5, ln = tid & 31;
    for (int r = 0; r < MM / 8; r++) {
        const int m = r * 8 + wrp;
        const float v0 = vs[m][ln], v1 = vs[m][ln + 32];
        float pa = fmaf(v1, w2s[ln + 32], v0 * w2s[ln]);
        float pb = fmaf(v1, w1s[ln + 32], v0 * w1s[ln]);
        float pg = fmaf(v1, bts[ln + 32], v0 * bts[ln]);
        #pragma unroll
        for (int o = 16; o > 0; o >>= 1) {
            pa += __shfl_xor_sync(0xFFFFFFFFu, pa, o);
            pb += __shfl_xor_sync(0xFFFFFFFFu, pb, o);
            pg += __shfl_xor_sync(0xFFFFFFFFu, pg, o);
        }
        if (ln == 0) {
            g_alpha[m] = pa * L2E; sa[m] = pa * L2E;
            g_beta[m]  = pb * L2E; sg[m] = pg * L2E;
        }
    }
    __syncthreads();
    if (tid == 0) {
        g_gammap[0] = 0.f;
        float run = 0.f, asum = 0.f;
        #pragma unroll
        for (int m = 0; m < MM; m++) { run += sg[m]; g_gammap[m + 1] = run; }
        #pragma unroll
        for (int m = 0; m < MR; m++) asum += sa[m];
        g_epsfold = asum * EPSF;
    }
}

// ---------------------------------------------------------------------------
// Kernel B: variance (ddof=1) + P precompute, register-blocked convolution.
// EPS contribution of all MR alpha taps folded in as a constant.
// ---------------------------------------------------------------------------
__global__ __launch_bounds__(256) void prep_kernel(const float* __restrict__ residuals,
                                                   const float* __restrict__ fc_b) {
    __shared__ float sh[SS];            // squared residuals
    __shared__ float beta_s[MM];
    __shared__ float gp_s[MM + 1];
    __shared__ float rs[8], rq[8];
    const int b = blockIdx.x;
    const int tid = threadIdx.x;
    const float4* __restrict__ row4 = (const float4*)(residuals + (size_t)b * SS);
    float4* __restrict__ sh4 = (float4*)sh;

    float sum = 0.f, sq = 0.f;
    for (int i = tid; i < SS / 4; i += 256) {
        float4 x = row4[i];
        sum += (x.x + x.y) + (x.z + x.w);
        float s0 = x.x * x.x, s1 = x.y * x.y, s2 = x.z * x.z, s3 = x.w * x.w;
        sq += (s0 + s1) + (s2 + s3);
        sh4[i] = make_float4(s0, s1, s2, s3);
    }
    if (tid < MM)     beta_s[tid] = g_beta[tid];
    if (tid < MM + 1) gp_s[tid]   = g_gammap[tid];

    #pragma unroll
    for (int o = 16; o > 0; o >>= 1) {
        sum += __shfl_xor_sync(0xFFFFFFFFu, sum, o);
        sq  += __shfl_xor_sync(0xFFFFFFFFu, sq,  o);
    }
    const int w = tid >> 5;
    if ((tid & 31) == 0) { rs[w] = sum; rq[w] = sq; }
    __syncthreads();

    if (tid == 0) {
        float ts = 0.f, tq = 0.f;
        #pragma unroll
        for (int i = 0; i < 8; i++) { ts += rs[i]; tq += rq[i]; }
        g_sig0[b] = (tq - ts * ts / (float)SS) / (float)(SS - 1);
    }

    // Register-blocked convolution: thread handles t in [tid*8, tid*8+8).
    const float fcb = fc_b[0] * L2E + g_epsfold;
    float* __restrict__ Prow = g_P + (size_t)b * SS;
    const int t0 = tid * 8;

    float wv[MM + 7];
    #pragma unroll
    for (int k = 0; k < MM + 7; k++) {
        int idx = t0 - MM + k;
        wv[k] = (idx >= 0) ? sh[idx] : 0.f;
    }
    float o8[8];
    #pragma unroll
    for (int jj = 0; jj < 8; jj++) {
        int t = t0 + jj;
        float acc = fcb + gp_s[t < MM ? t : MM];
        #pragma unroll
        for (int m = 0; m < MM; m++)
            acc = fmaf(beta_s[m], wv[jj + (MM - 1) - m], acc);
        o8[jj] = acc;
    }
    float4* __restrict__ Pv = (float4*)(Prow + t0);
    Pv[0] = make_float4(o8[0], o8[1], o8[2], o8[3]);
    Pv[1] = make_float4(o8[4], o8[5], o8[6], o8[7]);
}

// ---------------------------------------------------------------------------
// Kernel C: serial recurrence, 2 lanes per batch (A = lane<16, B = lane>=16).
// Ring stores u_t = lg2(1 + 2^{x2_t}); sigma_t = LN2*u_t + EPS (EPS folded in P).
// Chain: fma -> ex2 -> fadd -> lg2 (~40 cyc). Far taps m=3..11 produced 4/5
// steps ahead, split A/B, exchanged by one shfl_xor(16) per 2 steps.
// Near taps m=1,2 every step, m=3 on odd steps. Stores split A/B by group.
// ---------------------------------------------------------------------------
template <bool FIRST>
__device__ __forceinline__ void rec_block(
    float (&s)[32], float (&pend)[8], float& uc,
    float4& p4, const float4* __restrict__ Pv, float4* __restrict__ Ov, int base,
    const float (&c)[9], float a0r, float ar1, float ar2, float ar3,
    float sig0, bool laneA) {
    float4 cur, ov;
    #pragma unroll
    for (int j = 0; j < 32; j++) {
        if ((j & 3) == 0) { cur = p4; p4 = Pv[((base + j) >> 2) + 1]; }
        float px;
        if      ((j & 3) == 0) px = cur.x;
        else if ((j & 3) == 1) px = cur.y;
        else if ((j & 3) == 2) px = cur.z;
        else                   px = cur.w;

        // off-chain accumulator: P (+eps fold) + far partial + near taps
        float acc = px + pend[j & 7];
        acc = fmaf(ar1, s[(j + 30) & 31], acc);            // m=1: u_{t-2}
        acc = fmaf(ar2, s[(j + 29) & 31], acc);            // m=2: u_{t-3}
        if (j & 1) acc = fmaf(ar3, s[(j + 28) & 31], acc); // m=3 on odd t

        // chain: x2 -> ex2 -> 1+e -> lg2
        float x2 = fmaf(a0r, uc, acc);
        float e  = ex2f(x2);
        float u  = lg2f(1.f + e);
        float sig = fmaf(LN2, u, EPSF);
        if (FIRST && j == 0) { sig = sig0; u = L2E * (sig0 - EPSF); }
        uc = u;
        s[j & 31] = u;

        // far production every other step (targets j+4 / j+5)
        if ((j & 1) == 0) {
            float f0 = 0.f, f1 = 0.f, f2 = 0.f;
            #pragma unroll
            for (int i = 0; i < 9; i++) {
                float sv = s[(j + 32 - i) & 31];   // u_{t-i}
                if      ((i % 3) == 0) f0 = fmaf(c[i], sv, f0);
                else if ((i % 3) == 1) f1 = fmaf(c[i], sv, f1);
                else                   f2 = fmaf(c[i], sv, f2);
            }
            float fs = (f0 + f1) + f2;
            float other = __shfl_xor_sync(0xFFFFFFFFu, fs, 16);
            pend[(j + 4) & 7] = laneA ? fs : other;
            pend[(j + 5) & 7] = laneA ? other : fs;
        }

        if      ((j & 3) == 0) ov.x = sig;
        else if ((j & 3) == 1) ov.y = sig;
        else if ((j & 3) == 2) ov.z = sig;
        else                   ov.w = sig;
        if ((j & 3) == 3) {
            const bool mineA = (((j >> 2) & 1) == 0);
            if (mineA == laneA) Ov[(base + j) >> 2] = ov;
        }
    }
}

__global__ __launch_bounds__(32) void rec_kernel(float* __restrict__ out) {
    const int lane = threadIdx.x;
    const bool laneA = lane < 16;
    const int b = blockIdx.x * 16 + (lane & 15);

    // far coefficients (raw alpha = g_alpha * LN2):
    // laneA: m = 3..11 (9 taps, target t+4); laneB: m = 4..11 (+zero pad, target t+5)
    float c[9];
    #pragma unroll
    for (int i = 0; i < 9; i++) {
        int m = (laneA ? 3 : 4) + i;
        c[i] = (m < MR) ? g_alpha[m] * LN2 : 0.f;
    }
    const float a0r = g_alpha[0] * LN2;
    const float ar1 = g_alpha[1] * LN2;
    const float ar2 = g_alpha[2] * LN2;
    const float ar3 = g_alpha[3] * LN2;

    float s[32];
    #pragma unroll
    for (int i = 0; i < 32; i++) s[i] = 0.f;
    float pend[8];
    #pragma unroll
    for (int i = 0; i < 8; i++) pend[i] = 0.f;

    const float sig0 = g_sig0[b];
    float uc = 0.f;

    const float4* __restrict__ Pv = (const float4*)(g_P + (size_t)b * SS);
    float4* __restrict__ Ov = (float4*)(out + (size_t)b * SS);
    float4 p4 = Pv[0];

    rec_block<true>(s, pend, uc, p4, Pv, Ov, 0, c, a0r, ar1, ar2, ar3, sig0, laneA);
    for (int base = 32; base < SS; base += 32)
        rec_block<false>(s, pend, uc, p4, Pv, Ov, base, c, a0r, ar1, ar2, ar3, sig0, laneA);
}

// ---------------------------------------------------------------------------
extern "C" void kernel_launch(void* const* d_in, const int* in_sizes, int n_in,
                              void* d_out, int out_size) {
    const float* residuals = (const float*)d_in[0];  // (B,S)
    const float* W_ih_w    = (const float*)d_in[1];  // (H,2)
    const float* W_ih_b    = (const float*)d_in[2];  // (H,)
    const float* W_hh_w    = (const float*)d_in[3];  // (H,H)
    const float* W_hh_b    = (const float*)d_in[4];  // (H,)
    const float* fc_w      = (const float*)d_in[5];  // (1,H)
    const float* fc_b      = (const float*)d_in[6];  // (1,)
    float* out = (float*)d_out;                      // (B,S)

    setup_kernel<<<1, 256>>>(W_ih_w, W_ih_b, W_hh_w, W_hh_b, fc_w);
    prep_kernel<<<BB, 256>>>(residuals, fc_b);
    rec_kernel<<<BB / 16, 32>>>(out);
}